// round 7
// baseline (speedup 1.0000x reference)
#include <cuda_runtime.h>
#include <cuda_bf16.h>
#include <cstdint>

constexpr int Bsz  = 8;
constexpr int Cdim = 512;
constexpr int Ldim = 8192;
constexpr int Hn   = 8;
constexpr int Dh   = 64;

constexpr size_t XgN  = (size_t)Bsz * Cdim * Ldim;   // 33,554,432
constexpr size_t MatN = (size_t)Bsz * Cdim * Cdim;   // 2,097,152

// ---------------- scratch (static device arrays; no allocation) ----------------
__device__ __nv_bfloat16 g_XgH[XgN], g_XgL[XgN];     // x_global hi/lo [b][c][l]
__device__ float g_GpartF[4ull * MatN];              // fp32 gram split-K partials
__device__ float g_GpartM[2ull * MatN];              // HMMA gram split-K partials
__device__ float g_G[MatN];                          // arbitrated Gram
__device__ float g_kvpart[8ull * Bsz * Hn * Dh * Dh];
__device__ float g_W2[MatN];
__device__ float g_W3[MatN];

// ---------------- helpers ----------------
static __device__ __forceinline__ uint32_t s2u(const void* p) {
    uint32_t a;
    asm("{ .reg .u64 t; cvta.to.shared.u64 t, %1; cvt.u32.u64 %0, t; }" : "=r"(a) : "l"(p));
    return a;
}
static __device__ __forceinline__ uint32_t lds32(uint32_t addr) {
    uint32_t v;
    asm volatile("ld.shared.b32 %0, [%1];" : "=r"(v) : "r"(addr));
    return v;
}
static __device__ __forceinline__ void mma16816(float c[4], const uint32_t a[4],
                                                uint32_t b0, uint32_t b1) {
    asm volatile(
        "mma.sync.aligned.m16n8k16.row.col.f32.bf16.bf16.f32 "
        "{%0,%1,%2,%3}, {%4,%5,%6,%7}, {%8,%9}, {%0,%1,%2,%3};"
        : "+f"(c[0]), "+f"(c[1]), "+f"(c[2]), "+f"(c[3])
        : "r"(a[0]), "r"(a[1]), "r"(a[2]), "r"(a[3]), "r"(b0), "r"(b1));
}

// Smem tile geometry: 4 tiles (Ah,Al,Bh,Bl), 128 rows x 32 bf16, padded to 40.
constexpr int ROWE  = 40;          // elems per padded row
constexpr int TILEE = 128 * ROWE;
constexpr int ROWB  = 80;          // bytes per row (20 words: rows hit distinct banks)
constexpr int TILEB = 128 * ROWB;

// ---------------------------------------------------------------------------
// DIAGNOSTIC HMMA gram (no ldmatrix, no cp.async): fragments via ld.shared.b32.
// G[b] = Xg[b] @ Xg[b]^T, 128x128 tiles, 10 symmetric pairs, split-K=2 slabs
// into g_GpartM. 8 warps: wm=wid&1 (64 m-rows), wn=wid>>1 (32 n-cols).
// ---------------------------------------------------------------------------
__global__ __launch_bounds__(256) void gram_mma_lds() {
    __shared__ __align__(16) __nv_bfloat16 sm[4 * TILEE];
    const int pair = blockIdx.x, ks = blockIdx.y, b = blockIdx.z;
    int ti = 0, t = pair;
    while (t >= 4 - ti) { t -= 4 - ti; ti++; }
    const int tj = ti + t;

    const size_t bo = (size_t)b * Cdim * Ldim;
    const size_t ko = (size_t)ks * 4096;
    const __nv_bfloat16* srcs[4] = {
        g_XgH + bo + (size_t)ti * 128 * Ldim + ko,
        g_XgL + bo + (size_t)ti * 128 * Ldim + ko,
        g_XgH + bo + (size_t)tj * 128 * Ldim + ko,
        g_XgL + bo + (size_t)tj * 128 * Ldim + ko };

    const int tid = threadIdx.x, lane = tid & 31, wid = tid >> 5;
    const int wm = wid & 1, wn = wid >> 1;
    const uint32_t sb = s2u(sm);
    const int qr = lane >> 2;          // 0..7
    const int qc = (lane & 3) * 2;     // 0,2,4,6

    float acc[4][4][4];
#pragma unroll
    for (int i = 0; i < 4; i++)
#pragma unroll
        for (int j = 0; j < 4; j++)
#pragma unroll
            for (int q = 0; q < 4; q++) acc[i][j][q] = 0.f;

    for (int s = 0; s < 128; s++) {          // 4096 / 32
        const int kt = s << 5;
        __syncthreads();
#pragma unroll
        for (int sp = 0; sp < 4; sp++) {
#pragma unroll
            for (int q = 0; q < 2; q++) {
                const int id  = tid + q * 256;        // 0..511
                const int row = id >> 2, cc = id & 3; // 128 rows x 4 chunks
                *(uint4*)(sm + sp * TILEE + row * ROWE + cc * 8) =
                    *(const uint4*)(srcs[sp] + (size_t)row * Ldim + kt + cc * 8);
            }
        }
        __syncthreads();
#pragma unroll
        for (int ksub = 0; ksub < 2; ksub++) {
            const int kc2 = (ksub * 16 + qc) * 2;     // byte col offset
            uint32_t ah[4][4], al[4][4];
#pragma unroll
            for (int mi = 0; mi < 4; mi++) {
                const uint32_t b0 = sb + (uint32_t)((wm * 64 + mi * 16 + qr) * ROWB) + kc2;
                ah[mi][0] = lds32(b0);
                ah[mi][1] = lds32(b0 + 8 * ROWB);
                ah[mi][2] = lds32(b0 + 16);
                ah[mi][3] = lds32(b0 + 8 * ROWB + 16);
                al[mi][0] = lds32(b0 + TILEB);
                al[mi][1] = lds32(b0 + TILEB + 8 * ROWB);
                al[mi][2] = lds32(b0 + TILEB + 16);
                al[mi][3] = lds32(b0 + TILEB + 8 * ROWB + 16);
            }
#pragma unroll
            for (int nj = 0; nj < 4; nj++) {
                const uint32_t bo2 = sb + 2u * TILEB +
                    (uint32_t)((wn * 32 + nj * 8 + qr) * ROWB) + kc2;
                const uint32_t bh0 = lds32(bo2),          bh1 = lds32(bo2 + 16);
                const uint32_t bl0 = lds32(bo2 + TILEB),  bl1 = lds32(bo2 + TILEB + 16);
#pragma unroll
                for (int mi = 0; mi < 4; mi++) {
                    mma16816(acc[mi][nj], ah[mi], bh0, bh1);
                    mma16816(acc[mi][nj], al[mi], bh0, bh1);
                    mma16816(acc[mi][nj], ah[mi], bl0, bl1);
                }
            }
        }
    }

    const int tq = lane >> 2, tr2 = (lane & 3) * 2;
    float* Gp = g_GpartM + (size_t)ks * MatN + (size_t)b * Cdim * Cdim;
#pragma unroll
    for (int mi = 0; mi < 4; mi++) {
#pragma unroll
        for (int ni = 0; ni < 4; ni++) {
            const int m = ti * 128 + wm * 64 + mi * 16 + tq;
            const int n = tj * 128 + wn * 32 + ni * 8 + tr2;
            const float* c = acc[mi][ni];
            *(float2*)(Gp + (size_t)m * Cdim + n)       = make_float2(c[0], c[1]);
            *(float2*)(Gp + (size_t)(m + 8) * Cdim + n) = make_float2(c[2], c[3]);
            if (ti != tj) {
                Gp[(size_t)n * Cdim + m]           = c[0];
                Gp[(size_t)(n + 1) * Cdim + m]     = c[1];
                Gp[(size_t)n * Cdim + m + 8]       = c[2];
                Gp[(size_t)(n + 1) * Cdim + m + 8] = c[3];
            }
        }
    }
}

// ---------------------------------------------------------------------------
// fp32 Gram (proven R1/R2): split-K=4 into g_GpartF.
// ---------------------------------------------------------------------------
__global__ __launch_bounds__(256) void gram_kernel(const float* __restrict__ Xg) {
    const int pair = blockIdx.x, ks = blockIdx.y, b = blockIdx.z;
    int ti = 0, t = pair;
    while (t >= 4 - ti) { t -= 4 - ti; ti++; }
    const int tj = ti + t;

    const float* X   = Xg + (size_t)b * Cdim * Ldim;
    const float* Ag0 = X + (size_t)ti * 128 * Ldim;
    const float* Bg0 = X + (size_t)tj * 128 * Ldim;
    const int k0 = ks * 2048;

    __shared__ float As[16][132];
    __shared__ float Bs[16][132];

    const int tid = threadIdx.x;
    const int tx = tid & 15, ty = tid >> 4;
    const int lrow = tid >> 2, lc4 = tid & 3;

    float acc[8][8];
#pragma unroll
    for (int i = 0; i < 8; i++)
#pragma unroll
        for (int j = 0; j < 8; j++) acc[i][j] = 0.f;

    for (int kt = 0; kt < 2048; kt += 16) {
        const float* Ap = Ag0 + (size_t)(k0 + kt);
        const float* Bp = Bg0 + (size_t)(k0 + kt);
        float4 a0 = *(const float4*)(Ap + (size_t)lrow * Ldim + lc4 * 4);
        float4 a1 = *(const float4*)(Ap + (size_t)(lrow + 64) * Ldim + lc4 * 4);
        float4 b0 = *(const float4*)(Bp + (size_t)lrow * Ldim + lc4 * 4);
        float4 b1 = *(const float4*)(Bp + (size_t)(lrow + 64) * Ldim + lc4 * 4);
        __syncthreads();
        As[lc4*4+0][lrow]    = a0.x; As[lc4*4+1][lrow]    = a0.y;
        As[lc4*4+2][lrow]    = a0.z; As[lc4*4+3][lrow]    = a0.w;
        As[lc4*4+0][lrow+64] = a1.x; As[lc4*4+1][lrow+64] = a1.y;
        As[lc4*4+2][lrow+64] = a1.z; As[lc4*4+3][lrow+64] = a1.w;
        Bs[lc4*4+0][lrow]    = b0.x; Bs[lc4*4+1][lrow]    = b0.y;
        Bs[lc4*4+2][lrow]    = b0.z; Bs[lc4*4+3][lrow]    = b0.w;
        Bs[lc4*4+0][lrow+64] = b1.x; Bs[lc4*4+1][lrow+64] = b1.y;
        Bs[lc4*4+2][lrow+64] = b1.z; Bs[lc4*4+3][lrow+64] = b1.w;
        __syncthreads();
#pragma unroll
        for (int kk = 0; kk < 16; kk++) {
            float af[8], bf[8];
            *(float4*)&af[0] = *(const float4*)&As[kk][ty*4];
            *(float4*)&af[4] = *(const float4*)&As[kk][64 + ty*4];
            *(float4*)&bf[0] = *(const float4*)&Bs[kk][tx*4];
            *(float4*)&bf[4] = *(const float4*)&Bs[kk][64 + tx*4];
#pragma unroll
            for (int i = 0; i < 8; i++)
#pragma unroll
                for (int j = 0; j < 8; j++) acc[i][j] += af[i] * bf[j];
        }
    }

    float* Gp = g_GpartF + ((size_t)ks * Bsz + b) * Cdim * Cdim;
#pragma unroll
    for (int i = 0; i < 8; i++) {
        const int m = ti * 128 + ((i < 4) ? (ty*4 + i) : (64 + ty*4 + i - 4));
#pragma unroll
        for (int j = 0; j < 8; j++) {
            const int n = tj * 128 + ((j < 4) ? (tx*4 + j) : (64 + tx*4 + j - 4));
            Gp[(size_t)m * Cdim + n] = acc[i][j];
            if (ti != tj) Gp[(size_t)n * Cdim + m] = acc[i][j];
        }
    }
}

// ---------------------------------------------------------------------------
// Arbiter: g_G = HMMA result where it agrees with fp32, else fp32.
// Deterministic (pure function of inputs). rel_err of the run becomes the
// diagnostic: ~1e-6 => fp32 selected (HMMA broken); ~1e-5.. => HMMA selected.
// ---------------------------------------------------------------------------
__global__ void gsel_kernel() {
    const size_t idx = (size_t)blockIdx.x * blockDim.x + threadIdx.x;
    if (idx >= MatN) return;
    const float f = g_GpartF[idx] + g_GpartF[MatN + idx] +
                    g_GpartF[2 * MatN + idx] + g_GpartF[3 * MatN + idx];
    const float m = g_GpartM[idx] + g_GpartM[MatN + idx];
    const float tol = 1e-2f * (fabsf(f) + 1.0f);
    g_G[idx] = (fabsf(m - f) <= tol) ? m : f;
}

// ---------------------------------------------------------------------------
// Elementwise split fp32 -> bf16 hi/lo
// ---------------------------------------------------------------------------
__global__ void split_kernel(const float* __restrict__ src,
                             __nv_bfloat16* __restrict__ hi,
                             __nv_bfloat16* __restrict__ lo, size_t n4) {
    const size_t i = (size_t)blockIdx.x * blockDim.x + threadIdx.x;
    if (i >= n4) return;
    const float4 v = ((const float4*)src)[i];
    __nv_bfloat16 h0 = __float2bfloat16_rn(v.x), h1 = __float2bfloat16_rn(v.y);
    __nv_bfloat16 h2 = __float2bfloat16_rn(v.z), h3 = __float2bfloat16_rn(v.w);
    __nv_bfloat16 l0 = __float2bfloat16_rn(v.x - __bfloat162float(h0));
    __nv_bfloat16 l1 = __float2bfloat16_rn(v.y - __bfloat162float(h1));
    __nv_bfloat16 l2 = __float2bfloat16_rn(v.z - __bfloat162float(h2));
    __nv_bfloat16 l3 = __float2bfloat16_rn(v.w - __bfloat162float(h3));
    __nv_bfloat162 hA, hB, lA, lB;
    hA.x = h0; hA.y = h1; hB.x = h2; hB.y = h3;
    lA.x = l0; lA.y = l1; lB.x = l2; lB.y = l3;
    ((__nv_bfloat162*)hi)[i * 2]     = hA;
    ((__nv_bfloat162*)hi)[i * 2 + 1] = hB;
    ((__nv_bfloat162*)lo)[i * 2]     = lA;
    ((__nv_bfloat162*)lo)[i * 2 + 1] = lB;
}

// ---------------------------------------------------------------------------
// kv partials (fp32, proven): kv[b,h] = Wk_h @ G[b] @ Wv_h^T
// ---------------------------------------------------------------------------
__global__ __launch_bounds__(256) void kv_kernel(const float* __restrict__ Wk,
                                                 const float* __restrict__ Wv) {
    const int ct = blockIdx.x;
    const int h  = blockIdx.y;
    const int b  = blockIdx.z;
    const float* G = g_G + (size_t)b * Cdim * Cdim;
    const int c0 = ct * 64;

    __shared__ float Wks[16][68];
    __shared__ float Gs[16][68];
    __shared__ float Ts[64][68];
    __shared__ float Wvs[64][68];

    const int tid = threadIdx.x;
    const int tx = tid & 15, ty = tid >> 4;

    float acc[4][4];
#pragma unroll
    for (int i = 0; i < 4; i++)
#pragma unroll
        for (int j = 0; j < 4; j++) acc[i][j] = 0.f;

    for (int k = 0; k < 512; k += 16) {
        const int row = tid >> 2, c4 = tid & 3;
        float4 w4 = *(const float4*)(Wk + (size_t)(h*64 + row) * Cdim + k + c4*4);
        const int kr = tid >> 4, f4 = tid & 15;
        float4 g4 = *(const float4*)(G + (size_t)(k + kr) * Cdim + c0 + f4*4);
        __syncthreads();
        Wks[c4*4+0][row] = w4.x; Wks[c4*4+1][row] = w4.y;
        Wks[c4*4+2][row] = w4.z; Wks[c4*4+3][row] = w4.w;
        *(float4*)&Gs[kr][f4*4] = g4;
        __syncthreads();
#pragma unroll
        for (int kk = 0; kk < 16; kk++) {
            float a4[4], b4[4];
            *(float4*)&a4[0] = *(const float4*)&Wks[kk][ty*4];
            *(float4*)&b4[0] = *(const float4*)&Gs[kk][tx*4];
#pragma unroll
            for (int i = 0; i < 4; i++)
#pragma unroll
                for (int j = 0; j < 4; j++) acc[i][j] += a4[i] * b4[j];
        }
    }
#pragma unroll
    for (int i = 0; i < 4; i++)
#pragma unroll
        for (int j = 0; j < 4; j++) Ts[ty*4+i][tx*4+j] = acc[i][j];

#pragma unroll
    for (int q = 0; q < 4; q++) {
        const int idx = tid + q*256;
        const int er = idx >> 4, f4 = idx & 15;
        *(float4*)&Wvs[er][f4*4] = *(const float4*)(Wv + (size_t)(h*64 + er) * Cdim + c0 + f4*4);
    }
    __syncthreads();

    float acc2[4][4];
#pragma unroll
    for (int i = 0; i < 4; i++)
#pragma unroll
        for (int j = 0; j < 4; j++) acc2[i][j] = 0.f;
    for (int j = 0; j < 64; j++) {
        float a4[4], b4[4];
#pragma unroll
        for (int i = 0; i < 4; i++) a4[i] = Ts[ty*4+i][j];
#pragma unroll
        for (int e = 0; e < 4; e++) b4[e] = Wvs[tx*4+e][j];
#pragma unroll
        for (int i = 0; i < 4; i++)
#pragma unroll
            for (int e = 0; e < 4; e++) acc2[i][e] += a4[i] * b4[e];
    }
    float* kvp = g_kvpart + (((size_t)ct * Bsz + b) * Hn + h) * (Dh * Dh);
#pragma unroll
    for (int i = 0; i < 4; i++)
#pragma unroll
        for (int e = 0; e < 4; e++)
            kvp[(size_t)(ty*4 + i) * 64 + tx*4 + e] = acc2[i][e];
}

// ---------------------------------------------------------------------------
// W2 (fp32, proven)
// ---------------------------------------------------------------------------
__global__ __launch_bounds__(256) void w2_kernel(const float* __restrict__ Wo) {
    const int ot = blockIdx.x;
    const int h  = blockIdx.y;
    const int b  = blockIdx.z;

    __shared__ float Wos[64][68];
    __shared__ float kvs[64][68];

    const int tid = threadIdx.x;
    const int tx = tid & 15, ty = tid >> 4;

#pragma unroll
    for (int q = 0; q < 4; q++) {
        const int idx = tid + q*256;
        const int r = idx >> 4, f4 = idx & 15;
        *(float4*)&Wos[r][f4*4] = *(const float4*)(Wo + (size_t)(ot*64 + r) * Cdim + h*64 + f4*4);
    }
#pragma unroll
    for (int q = 0; q < 4; q++) {
        const int idx = tid + q*256;
        const int d = idx >> 4, f4 = idx & 15;
        float4 s = make_float4(0.f, 0.f, 0.f, 0.f);
        for (int t = 0; t < 8; t++) {
            const float4 v = *(const float4*)(g_kvpart +
                (((size_t)t * Bsz + b) * Hn + h) * 4096 + (size_t)d * 64 + f4*4);
            s.x += v.x; s.y += v.y; s.z += v.z; s.w += v.w;
        }
        *(float4*)&kvs[d][f4*4] = s;
    }
    __syncthreads();

    float acc[4][4];
#pragma unroll
    for (int i = 0; i < 4; i++)
#pragma unroll
        for (int j = 0; j < 4; j++) acc[i][j] = 0.f;
    for (int e = 0; e < 64; e++) {
        float a4[4], b4[4];
#pragma unroll
        for (int i = 0; i < 4; i++) a4[i] = Wos[ty*4+i][e];
#pragma unroll
        for (int j = 0; j < 4; j++) b4[j] = kvs[tx*4+j][e];
#pragma unroll
        for (int i = 0; i < 4; i++)
#pragma unroll
            for (int j = 0; j < 4; j++) acc[i][j] += a4[i] * b4[j];
    }
    float* W2 = g_W2 + (size_t)b * Cdim * Cdim;
    const float inv = 1.f / 64.f;
#pragma unroll
    for (int i = 0; i < 4; i++)
#pragma unroll
        for (int j = 0; j < 4; j++)
            W2[(size_t)(ot*64 + ty*4 + i) * Cdim + h*64 + tx*4 + j] = acc[i][j] * inv;
}

// ---------------------------------------------------------------------------
// W3 (fp32, proven): W3[b] = W2[b] @ Wq
// ---------------------------------------------------------------------------
__global__ __launch_bounds__(256) void w3_kernel(const float* __restrict__ Wq) {
    const int nt = blockIdx.x;
    const int mt = blockIdx.y;
    const int b  = blockIdx.z;
    const float* A = g_W2 + (size_t)b * Cdim * Cdim;

    __shared__ float As_[16][68];
    __shared__ float Bs_[16][68];

    const int tid = threadIdx.x;
    const int tx = tid & 15, ty = tid >> 4;

    float acc[4][4];
#pragma unroll
    for (int i = 0; i < 4; i++)
#pragma unroll
        for (int j = 0; j < 4; j++) acc[i][j] = 0.f;

    for (int k = 0; k < 512; k += 16) {
        const int row = tid >> 2, c4 = tid & 3;
        float4 a4 = *(const float4*)(A + (size_t)(mt*64 + row) * Cdim + k + c4*4);
        const int kr = tid >> 4, f4 = tid & 15;
        float4 b4 = *(const float4*)(Wq + (size_t)(k + kr) * Cdim + nt*64 + f4*4);
        __syncthreads();
        As_[c4*4+0][row] = a4.x; As_[c4*4+1][row] = a4.y;
        As_[c4*4+2][row] = a4.z; As_[c4*4+3][row] = a4.w;
        *(float4*)&Bs_[kr][f4*4] = b4;
        __syncthreads();
#pragma unroll
        for (int kk = 0; kk < 16; kk++) {
            float a[4], bb[4];
            *(float4*)&a[0]  = *(const float4*)&As_[kk][ty*4];
            *(float4*)&bb[0] = *(const float4*)&Bs_[kk][tx*4];
#pragma unroll
            for (int i = 0; i < 4; i++)
#pragma unroll
                for (int j = 0; j < 4; j++) acc[i][j] += a[i] * bb[j];
        }
    }
    float* W3 = g_W3 + (size_t)b * Cdim * Cdim;
#pragma unroll
    for (int i = 0; i < 4; i++)
#pragma unroll
        for (int j = 0; j < 4; j++)
            W3[(size_t)(mt*64 + ty*4 + i) * Cdim + nt*64 + tx*4 + j] = acc[i][j];
}

// ---------------------------------------------------------------------------
// out[b] = W3[b] @ Xl[b] (fp32, proven)
// ---------------------------------------------------------------------------
__global__ __launch_bounds__(256) void out_kernel(const float* __restrict__ Xl,
                                                  float* __restrict__ Out) {
    const int nt = blockIdx.x;
    const int mt = blockIdx.y;
    const int b  = blockIdx.z;
    const float* A  = g_W3 + (size_t)b * Cdim * Cdim;
    const float* Bm = Xl + (size_t)b * Cdim * Ldim;
    float* O        = Out + (size_t)b * Cdim * Ldim;

    __shared__ float As[16][132];
    __shared__ float Bs[16][132];

    const int tid = threadIdx.x;
    const int tx = tid & 15, ty = tid >> 4;
    const int arow = tid >> 2, ac4 = tid & 3;
    const int kr0 = tid >> 5, c40 = tid & 31;
    const int n0 = nt * 128;

    float acc[8][8];
#pragma unroll
    for (int i = 0; i < 8; i++)
#pragma unroll
        for (int j = 0; j < 8; j++) acc[i][j] = 0.f;

    for (int k = 0; k < 512; k += 16) {
        float4 a0 = *(const float4*)(A + (size_t)(mt*128 + arow) * Cdim + k + ac4*4);
        float4 a1 = *(const float4*)(A + (size_t)(mt*128 + arow + 64) * Cdim + k + ac4*4);
        float4 b0 = *(const float4*)(Bm + (size_t)(k + kr0) * Ldim + n0 + c40*4);
        float4 b1 = *(const float4*)(Bm + (size_t)(k + kr0 + 8) * Ldim + n0 + c40*4);
        __syncthreads();
        As[ac4*4+0][arow]    = a0.x; As[ac4*4+1][arow]    = a0.y;
        As[ac4*4+2][arow]    = a0.z; As[ac4*4+3][arow]    = a0.w;
        As[ac4*4+0][arow+64] = a1.x; As[ac4*4+1][arow+64] = a1.y;
        As[ac4*4+2][arow+64] = a1.z; As[ac4*4+3][arow+64] = a1.w;
        *(float4*)&Bs[kr0][c40*4]     = b0;
        *(float4*)&Bs[kr0 + 8][c40*4] = b1;
        __syncthreads();
#pragma unroll
        for (int kk = 0; kk < 16; kk++) {
            float af[8], bf[8];
            *(float4*)&af[0] = *(const float4*)&As[kk][ty*4];
            *(float4*)&af[4] = *(const float4*)&As[kk][64 + ty*4];
            *(float4*)&bf[0] = *(const float4*)&Bs[kk][tx*4];
            *(float4*)&bf[4] = *(const float4*)&Bs[kk][64 + tx*4];
#pragma unroll
            for (int i = 0; i < 8; i++)
#pragma unroll
                for (int j = 0; j < 8; j++) acc[i][j] += af[i] * bf[j];
        }
    }

#pragma unroll
    for (int i = 0; i < 8; i++) {
        const int m = mt*128 + ((i < 4) ? (ty*4 + i) : (64 + ty*4 + i - 4));
        float4 v0 = make_float4(acc[i][0], acc[i][1], acc[i][2], acc[i][3]);
        float4 v1 = make_float4(acc[i][4], acc[i][5], acc[i][6], acc[i][7]);
        *(float4*)(O + (size_t)m * Ldim + n0 + tx*4)      = v0;
        *(float4*)(O + (size_t)m * Ldim + n0 + 64 + tx*4) = v1;
    }
}

// ---------------------------------------------------------------------------
extern "C" void kernel_launch(void* const* d_in, const int* in_sizes, int n_in,
                              void* d_out, int out_size) {
    const float* x_local  = (const float*)d_in[0];
    const float* x_global = (const float*)d_in[1];
    const float* Wq       = (const float*)d_in[2];
    const float* Wk       = (const float*)d_in[3];
    const float* Wv       = (const float*)d_in[4];
    const float* Wo       = (const float*)d_in[5];
    float* out = (float*)d_out;

    // HMMA diagnostic path (scratch-only until arbitration)
    split_kernel<<<(unsigned)((XgN/4 + 255) / 256), 256>>>(x_global, g_XgH, g_XgL, XgN/4);
    gram_mma_lds<<<dim3(10, 2, Bsz), 256>>>();
    // Proven fp32 path
    gram_kernel<<<dim3(10, 4, Bsz), 256>>>(x_global);
    // Deterministic arbitration: HMMA values only where they agree with fp32
    gsel_kernel<<<(unsigned)((MatN + 255) / 256), 256>>>();
    kv_kernel<<<dim3(8, 8, 8), 256>>>(Wk, Wv);
    w2_kernel<<<dim3(8, 8, 8), 256>>>(Wo);
    w3_kernel<<<dim3(8, 8, 8), 256>>>(Wq);
    out_kernel<<<dim3(64, 4, 8), 256>>>(x_local, out);
}